// round 14
// baseline (speedup 1.0000x reference)
#include <cuda_runtime.h>
#include <cuda_bf16.h>
#include <math.h>

#define N_NODES 100000
#define IN_DIM  128
#define HID     64
#define NCLS    40
#define N_EDGES 1600000
#define CHUNK   512
#define NCHUNK  ((N_NODES + CHUNK - 1) / CHUNK)   // 196

// Scratch (__device__ globals per alloc-free rule)
__device__ float g_A[(size_t)N_NODES * HID];
__device__ float g_B[(size_t)N_NODES * HID];
__device__ int   g_cnt[N_NODES];
__device__ int   g_ptr[N_NODES + 1];
__device__ int   g_partials[NCHUNK];
__device__ int2  g_csr[N_EDGES];

// ---------------------------------------------------------------------------
// CSR construction (unchanged; block_scan stays at launch position 4 = env marker)
// ---------------------------------------------------------------------------
__global__ void zero_int_kernel(int* __restrict__ p, int n) {
    int i = blockIdx.x * blockDim.x + threadIdx.x;
    if (i < n) p[i] = 0;
}

__global__ void hist_kernel(const int* __restrict__ er, int* __restrict__ cnt, int E) {
    int e = blockIdx.x * blockDim.x + threadIdx.x;
    if (e < E) atomicAdd(&cnt[er[e]], 1);
}

__global__ void chunk_reduce_kernel(const int* __restrict__ cnt, int* __restrict__ partials, int N) {
    __shared__ int s[CHUNK];
    int t = threadIdx.x;
    int i = blockIdx.x * CHUNK + t;
    s[t] = (i < N) ? cnt[i] : 0;
    __syncthreads();
    for (int off = CHUNK / 2; off > 0; off >>= 1) {
        if (t < off) s[t] += s[t + off];
        __syncthreads();
    }
    if (t == 0) partials[blockIdx.x] = s[0];
}

__global__ void block_scan_kernel(const int* __restrict__ cnt,
                                  const int* __restrict__ partials,
                                  int* __restrict__ ptr, int* __restrict__ cur,
                                  int N, int E) {
    __shared__ int s[CHUNK];
    __shared__ int p[256];
    int t = threadIdx.x;

    if (t < 256) p[t] = (t < NCHUNK) ? partials[t] : 0;
    __syncthreads();
#pragma unroll
    for (int off = 1; off < 256; off <<= 1) {
        int x = (t < 256 && t >= off) ? p[t - off] : 0;
        __syncthreads();
        if (t < 256) p[t] += x;
        __syncthreads();
    }
    const int chunkOff = (blockIdx.x == 0) ? 0 : p[blockIdx.x - 1];

    int i = blockIdx.x * CHUNK + t;
    int c = (i < N) ? cnt[i] : 0;
    s[t] = c;
    __syncthreads();
#pragma unroll
    for (int off = 1; off < CHUNK; off <<= 1) {
        int x = (t >= off) ? s[t - off] : 0;
        __syncthreads();
        s[t] += x;
        __syncthreads();
    }
    if (i < N) {
        int start = chunkOff + s[t] - c;
        ptr[i] = start;
        cur[i] = start;
        if (i == N - 1) ptr[N] = E;
    }
}

__global__ void scatter_kernel(const int* __restrict__ er, const int* __restrict__ ec,
                               const float* __restrict__ ev,
                               int* __restrict__ cur, int2* __restrict__ csr, int E) {
    int e = blockIdx.x * blockDim.x + threadIdx.x;
    if (e < E) {
        int pos = atomicAdd(&cur[er[e]], 1);
        csr[pos] = make_int2(ec[e], __float_as_int(ev[e]));
    }
}

// ---------------------------------------------------------------------------
// Tiled GEMM (R4 scalar, conflict-free smem) — layer 1: support1 = x@W1+b1
// ---------------------------------------------------------------------------
template<int K, bool RELU>
__global__ void gemm64_kernel(const float* __restrict__ X,
                              const float* __restrict__ W,
                              const float* __restrict__ b,
                              float* __restrict__ C, int N) {
    constexpr int BK = 32;
    __shared__ float Xs[64][BK + 1];
    __shared__ float Ws[BK][64];

    const int tid = threadIdx.x;
    const int tx = tid & 15;
    const int ty = tid >> 4;
    const int nodeBase = blockIdx.x * 64;

    float acc[4][4];
    const float4 bv = *reinterpret_cast<const float4*>(b + tx * 4);
#pragma unroll
    for (int i = 0; i < 4; i++) {
        acc[i][0] = bv.x; acc[i][1] = bv.y; acc[i][2] = bv.z; acc[i][3] = bv.w;
    }

    for (int kc = 0; kc < K; kc += BK) {
#pragma unroll
        for (int t = 0; t < 2; t++) {
            int idx = tid + t * 256;
            int r   = idx >> 3;
            int c4  = idx & 7;
            int node = nodeBase + r;
            float4 xv = make_float4(0.f, 0.f, 0.f, 0.f);
            if (node < N)
                xv = *reinterpret_cast<const float4*>(X + (size_t)node * K + kc + c4 * 4);
            if (RELU) {
                xv.x = fmaxf(xv.x, 0.f); xv.y = fmaxf(xv.y, 0.f);
                xv.z = fmaxf(xv.z, 0.f); xv.w = fmaxf(xv.w, 0.f);
            }
            Xs[r][c4 * 4 + 0] = xv.x;
            Xs[r][c4 * 4 + 1] = xv.y;
            Xs[r][c4 * 4 + 2] = xv.z;
            Xs[r][c4 * 4 + 3] = xv.w;
        }
#pragma unroll
        for (int t = 0; t < 2; t++) {
            int idx = tid + t * 256;
            int r   = idx >> 4;
            int c4  = idx & 15;
            *reinterpret_cast<float4*>(&Ws[r][c4 * 4]) =
                *reinterpret_cast<const float4*>(W + (size_t)(kc + r) * 64 + c4 * 4);
        }
        __syncthreads();

#pragma unroll
        for (int kk = 0; kk < BK; kk++) {
            const float4 wv = *reinterpret_cast<const float4*>(&Ws[kk][tx * 4]);
            float xv[4];
#pragma unroll
            for (int i = 0; i < 4; i++) xv[i] = Xs[ty * 4 + i][kk];
#pragma unroll
            for (int i = 0; i < 4; i++) {
                acc[i][0] += xv[i] * wv.x;
                acc[i][1] += xv[i] * wv.y;
                acc[i][2] += xv[i] * wv.z;
                acc[i][3] += xv[i] * wv.w;
            }
        }
        __syncthreads();
    }

#pragma unroll
    for (int i = 0; i < 4; i++) {
        int node = nodeBase + ty * 4 + i;
        if (node < N) {
            float4 o = make_float4(acc[i][0], acc[i][1], acc[i][2], acc[i][3]);
            *reinterpret_cast<float4*>(C + (size_t)node * 64 + tx * 4) = o;
        }
    }
}

// ---------------------------------------------------------------------------
// Fused SpMM1 + GEMM2, 64-row blocks (fixes R11's W2-reload flaw):
//   Stage 1: h1 rows = gather (4 passes x 16 rows), relu, -> hs[64][76] smem.
//   Stage 2: support2 = hs @ W2 + b2 using the proven R4 GEMM inner loop,
//            W2 chunked 32 rows (8KB) x2, amortized over a 64-row tile.
// hs stride 76: float4-aligned stores; stage-2 broadcast rows (step 4) are
// 4*76 = 304 ≡ 16 (mod 32) banks apart -> conflict-free.
// ---------------------------------------------------------------------------
__global__ void spmm1_gemm2_kernel(const int* __restrict__ ptr,
                                   const int2* __restrict__ csr,
                                   const float* __restrict__ D,
                                   const float* __restrict__ W2,
                                   const float* __restrict__ b2,
                                   float* __restrict__ O, int N) {
    __shared__ float hs[64][76];
    __shared__ float Ws[32][64];
    __shared__ float bsm[64];

    const int tid  = threadIdx.x;
    const int lane = tid & 31;
    const int warp = tid >> 5;
    const int g = lane >> 4;
    const int h = lane & 15;
    const int rowBase = blockIdx.x * 64;

    if (tid < 64) bsm[tid] = b2[tid];

    // ---- Stage 1: gather 64 rows (4 passes x 8 warps x 2 rows) ----
#pragma unroll
    for (int pass = 0; pass < 4; pass++) {
        const int localRow = pass * 16 + warp * 2 + g;
        const int row = rowBase + localRow;
        if (row < N) {
            const int start = ptr[row];
            const int end   = ptr[row + 1];

            float4 acc = make_float4(0.f, 0.f, 0.f, 0.f);
            int j = start;

            for (; j + 4 <= end; j += 4) {
                const int2 m0 = __ldg(&csr[j]);
                const int2 m1 = __ldg(&csr[j + 1]);
                const int2 m2 = __ldg(&csr[j + 2]);
                const int2 m3 = __ldg(&csr[j + 3]);
                const float4 a0 = *(reinterpret_cast<const float4*>(D + (size_t)m0.x * 64) + h);
                const float4 a1 = *(reinterpret_cast<const float4*>(D + (size_t)m1.x * 64) + h);
                const float4 a2 = *(reinterpret_cast<const float4*>(D + (size_t)m2.x * 64) + h);
                const float4 a3 = *(reinterpret_cast<const float4*>(D + (size_t)m3.x * 64) + h);
                const float v0 = __int_as_float(m0.y), v1 = __int_as_float(m1.y);
                const float v2 = __int_as_float(m2.y), v3 = __int_as_float(m3.y);
                acc.x += v0 * a0.x; acc.y += v0 * a0.y; acc.z += v0 * a0.z; acc.w += v0 * a0.w;
                acc.x += v1 * a1.x; acc.y += v1 * a1.y; acc.z += v1 * a1.z; acc.w += v1 * a1.w;
                acc.x += v2 * a2.x; acc.y += v2 * a2.y; acc.z += v2 * a2.z; acc.w += v2 * a2.w;
                acc.x += v3 * a3.x; acc.y += v3 * a3.y; acc.z += v3 * a3.z; acc.w += v3 * a3.w;
            }
            for (; j < end; j++) {
                const int2 m = __ldg(&csr[j]);
                const float v = __int_as_float(m.y);
                const float4 a = *(reinterpret_cast<const float4*>(D + (size_t)m.x * 64) + h);
                acc.x += v * a.x; acc.y += v * a.y; acc.z += v * a.z; acc.w += v * a.w;
            }

            // relu fused (h1's only consumer is GEMM2)
            acc.x = fmaxf(acc.x, 0.f); acc.y = fmaxf(acc.y, 0.f);
            acc.z = fmaxf(acc.z, 0.f); acc.w = fmaxf(acc.w, 0.f);
            *reinterpret_cast<float4*>(&hs[localRow][h * 4]) = acc;
        }
    }
    __syncthreads();

    // ---- Stage 2: support2[64][64] = hs @ W2 + b2 (R4 GEMM inner loop) ----
    const int tx = tid & 15;
    const int ty = tid >> 4;

    float acc[4][4];
    const float4 bv = *reinterpret_cast<const float4*>(&bsm[tx * 4]);
#pragma unroll
    for (int i = 0; i < 4; i++) {
        acc[i][0] = bv.x; acc[i][1] = bv.y; acc[i][2] = bv.z; acc[i][3] = bv.w;
    }

    for (int kc = 0; kc < HID; kc += 32) {
        // Load W2 chunk: 32 rows x 64 cols = 512 float4, 2 per thread.
#pragma unroll
        for (int t = 0; t < 2; t++) {
            int idx = tid + t * 256;
            int r   = idx >> 4;
            int c4  = idx & 15;
            *reinterpret_cast<float4*>(&Ws[r][c4 * 4]) =
                *reinterpret_cast<const float4*>(W2 + (size_t)(kc + r) * 64 + c4 * 4);
        }
        __syncthreads();

#pragma unroll
        for (int kk = 0; kk < 32; kk++) {
            const float4 wv = *reinterpret_cast<const float4*>(&Ws[kk][tx * 4]);
            float xv[4];
#pragma unroll
            for (int i = 0; i < 4; i++) xv[i] = hs[ty * 4 + i][kc + kk];
#pragma unroll
            for (int i = 0; i < 4; i++) {
                acc[i][0] += xv[i] * wv.x;
                acc[i][1] += xv[i] * wv.y;
                acc[i][2] += xv[i] * wv.z;
                acc[i][3] += xv[i] * wv.w;
            }
        }
        __syncthreads();
    }

#pragma unroll
    for (int i = 0; i < 4; i++) {
        int node = rowBase + ty * 4 + i;
        if (node < N) {
            float4 o = make_float4(acc[i][0], acc[i][1], acc[i][2], acc[i][3]);
            *reinterpret_cast<float4*>(O + (size_t)node * 64 + tx * 4) = o;
        }
    }
}

// ---------------------------------------------------------------------------
// Fused SpMM2 + classifier (R10, unchanged)
// ---------------------------------------------------------------------------
__global__ void spmm_classifier_kernel(const int* __restrict__ ptr,
                                       const int2* __restrict__ csr,
                                       const float* __restrict__ D,
                                       const float* __restrict__ Wc,
                                       const float* __restrict__ bc,
                                       float* __restrict__ out, int N) {
    __shared__ float  hs[16][64];
    __shared__ float2 Wp[64][32];
    __shared__ float  bs[40];

    const int tid  = threadIdx.x;
    const int lane = tid & 31;
    const int warp = tid >> 5;
    const int g = lane >> 4;
    const int h = lane & 15;

    for (int i = tid; i < 64 * 32; i += 256) {
        int k = i >> 5, l = i & 31;
        float w0 = Wc[k * 40 + l];
        float w1 = (l < 8) ? Wc[k * 40 + 32 + l] : 0.f;
        Wp[k][l] = make_float2(w0, w1);
    }
    if (tid < 40) bs[tid] = bc[tid];

    const int localRow = warp * 2 + g;
    const int row = blockIdx.x * 16 + localRow;

    if (row < N) {
        const int start = ptr[row];
        const int end   = ptr[row + 1];

        float4 acc = make_float4(0.f, 0.f, 0.f, 0.f);
        int j = start;

        for (; j + 4 <= end; j += 4) {
            const int2 m0 = __ldg(&csr[j]);
            const int2 m1 = __ldg(&csr[j + 1]);
            const int2 m2 = __ldg(&csr[j + 2]);
            const int2 m3 = __ldg(&csr[j + 3]);
            const float4 a0 = *(reinterpret_cast<const float4*>(D + (size_t)m0.x * 64) + h);
            const float4 a1 = *(reinterpret_cast<const float4*>(D + (size_t)m1.x * 64) + h);
            const float4 a2 = *(reinterpret_cast<const float4*>(D + (size_t)m2.x * 64) + h);
            const float4 a3 = *(reinterpret_cast<const float4*>(D + (size_t)m3.x * 64) + h);
            const float v0 = __int_as_float(m0.y), v1 = __int_as_float(m1.y);
            const float v2 = __int_as_float(m2.y), v3 = __int_as_float(m3.y);
            acc.x += v0 * a0.x; acc.y += v0 * a0.y; acc.z += v0 * a0.z; acc.w += v0 * a0.w;
            acc.x += v1 * a1.x; acc.y += v1 * a1.y; acc.z += v1 * a1.z; acc.w += v1 * a1.w;
            acc.x += v2 * a2.x; acc.y += v2 * a2.y; acc.z += v2 * a2.z; acc.w += v2 * a2.w;
            acc.x += v3 * a3.x; acc.y += v3 * a3.y; acc.z += v3 * a3.z; acc.w += v3 * a3.w;
        }
        for (; j < end; j++) {
            const int2 m = __ldg(&csr[j]);
            const float v = __int_as_float(m.y);
            const float4 a = *(reinterpret_cast<const float4*>(D + (size_t)m.x * 64) + h);
            acc.x += v * a.x; acc.y += v * a.y; acc.z += v * a.z; acc.w += v * a.w;
        }

        *reinterpret_cast<float4*>(&hs[localRow][h * 4]) = acc;
    }
    __syncthreads();

#pragma unroll
    for (int it = 0; it < 2; it++) {
        const int r = warp * 2 + it;
        const int node = blockIdx.x * 16 + r;
        if (node < N) {
            float v0 = bs[lane];
            float v1 = (lane < 8) ? bs[32 + lane] : 0.f;
#pragma unroll
            for (int k = 0; k < 64; k++) {
                const float hv = hs[r][k];
                const float2 w = Wp[k][lane];
                v0 += hv * w.x;
                v1 += hv * w.y;
            }

            float m = (lane < 8) ? fmaxf(v0, v1) : v0;
#pragma unroll
            for (int off = 16; off; off >>= 1)
                m = fmaxf(m, __shfl_xor_sync(0xffffffffu, m, off));
            float s = expf(v0 - m) + ((lane < 8) ? expf(v1 - m) : 0.f);
#pragma unroll
            for (int off = 16; off; off >>= 1)
                s += __shfl_xor_sync(0xffffffffu, s, off);
            const float lse = m + logf(s);

            out[(size_t)node * 40 + lane] = v0 - lse;
            if (lane < 8)
                out[(size_t)node * 40 + 32 + lane] = v1 - lse;
        }
    }
}

// ---------------------------------------------------------------------------
// launch (single stream; block_scan back at position 4 = env marker)
// ---------------------------------------------------------------------------
extern "C" void kernel_launch(void* const* d_in, const int* in_sizes, int n_in,
                              void* d_out, int out_size) {
    const float* x  = (const float*)d_in[0];
    const int*   er = (const int*)  d_in[1];
    const int*   ec = (const int*)  d_in[2];
    const float* ev = (const float*)d_in[3];
    const float* W1 = (const float*)d_in[4];
    const float* b1 = (const float*)d_in[5];
    const float* W2 = (const float*)d_in[6];
    const float* b2 = (const float*)d_in[7];
    const float* Wc = (const float*)d_in[8];
    const float* bc = (const float*)d_in[9];
    float* out = (float*)d_out;

    const int N = in_sizes[0] / IN_DIM;   // 100000
    const int E = in_sizes[1];            // 1600000

    void *pA_, *pB_, *pCnt_, *pPtr_, *pPar_, *pCsr_;
    cudaGetSymbolAddress(&pA_, g_A);
    cudaGetSymbolAddress(&pB_, g_B);
    cudaGetSymbolAddress(&pCnt_, g_cnt);
    cudaGetSymbolAddress(&pPtr_, g_ptr);
    cudaGetSymbolAddress(&pPar_, g_partials);
    cudaGetSymbolAddress(&pCsr_, g_csr);
    float* A   = (float*)pA_;
    float* B   = (float*)pB_;
    int*   cnt = (int*)pCnt_;
    int*   ptr = (int*)pPtr_;
    int*   par = (int*)pPar_;
    int2*  csr = (int2*)pCsr_;

    const int gemmBlocks = (N + 63) / 64;     // 1563
    const int eBlocks    = (E + 255) / 256;
    const int spmmBlocks = (N + 15) / 16;

    // --- CSR build (positions 1-5; block_scan = env marker at 4) ---
    zero_int_kernel<<<(N + 255) / 256, 256>>>(cnt, N);
    hist_kernel<<<eBlocks, 256>>>(er, cnt, E);
    chunk_reduce_kernel<<<NCHUNK, CHUNK>>>(cnt, par, N);
    block_scan_kernel<<<NCHUNK, CHUNK>>>(cnt, par, ptr, cnt /*cursor*/, N, E);
    scatter_kernel<<<eBlocks, 256>>>(er, ec, ev, cnt, csr, E);

    // --- Layer 1: support1 = x@W1+b1 ---
    gemm64_kernel<IN_DIM, false><<<gemmBlocks, 256>>>(x, W1, b1, A, N);

    // --- Fused SpMM1 + GEMM2 (64-row blocks): B = relu(spmm(A)) @ W2 + b2 ---
    spmm1_gemm2_kernel<<<gemmBlocks, 256>>>(ptr, csr, A, W2, b2, B, N);

    // --- Fused SpMM2 + classifier ---
    spmm_classifier_kernel<<<spmmBlocks, 256>>>(ptr, csr, B, Wc, bc, out, N);
}

// round 15
// speedup vs baseline: 1.0559x; 1.0559x over previous
#include <cuda_runtime.h>
#include <cuda_fp16.h>
#include <math.h>

#define N_NODES 100000
#define IN_DIM  128
#define HID     64
#define NCLS    40
#define N_EDGES 1600000
#define CHUNK   512
#define NCHUNK  ((N_NODES + CHUNK - 1) / CHUNK)   // 196

// Scratch (__device__ globals per alloc-free rule)
__device__ __half g_h[(size_t)N_NODES * HID];   // fp16 support buffer (reused layer1/layer2)
__device__ float  g_B[(size_t)N_NODES * HID];   // fp32 h1 buffer
__device__ int    g_cnt[N_NODES];
__device__ int    g_ptr[N_NODES + 1];
__device__ int    g_partials[NCHUNK];
__device__ int2   g_csr[N_EDGES];

// ---------------------------------------------------------------------------
// CSR construction (unchanged; block_scan at launch position 4 = env marker)
// ---------------------------------------------------------------------------
__global__ void zero_int_kernel(int* __restrict__ p, int n) {
    int i = blockIdx.x * blockDim.x + threadIdx.x;
    if (i < n) p[i] = 0;
}

__global__ void hist_kernel(const int* __restrict__ er, int* __restrict__ cnt, int E) {
    int e = blockIdx.x * blockDim.x + threadIdx.x;
    if (e < E) atomicAdd(&cnt[er[e]], 1);
}

__global__ void chunk_reduce_kernel(const int* __restrict__ cnt, int* __restrict__ partials, int N) {
    __shared__ int s[CHUNK];
    int t = threadIdx.x;
    int i = blockIdx.x * CHUNK + t;
    s[t] = (i < N) ? cnt[i] : 0;
    __syncthreads();
    for (int off = CHUNK / 2; off > 0; off >>= 1) {
        if (t < off) s[t] += s[t + off];
        __syncthreads();
    }
    if (t == 0) partials[blockIdx.x] = s[0];
}

__global__ void block_scan_kernel(const int* __restrict__ cnt,
                                  const int* __restrict__ partials,
                                  int* __restrict__ ptr, int* __restrict__ cur,
                                  int N, int E) {
    __shared__ int s[CHUNK];
    __shared__ int p[256];
    int t = threadIdx.x;

    if (t < 256) p[t] = (t < NCHUNK) ? partials[t] : 0;
    __syncthreads();
#pragma unroll
    for (int off = 1; off < 256; off <<= 1) {
        int x = (t < 256 && t >= off) ? p[t - off] : 0;
        __syncthreads();
        if (t < 256) p[t] += x;
        __syncthreads();
    }
    const int chunkOff = (blockIdx.x == 0) ? 0 : p[blockIdx.x - 1];

    int i = blockIdx.x * CHUNK + t;
    int c = (i < N) ? cnt[i] : 0;
    s[t] = c;
    __syncthreads();
#pragma unroll
    for (int off = 1; off < CHUNK; off <<= 1) {
        int x = (t >= off) ? s[t - off] : 0;
        __syncthreads();
        s[t] += x;
        __syncthreads();
    }
    if (i < N) {
        int start = chunkOff + s[t] - c;
        ptr[i] = start;
        cur[i] = start;
        if (i == N - 1) ptr[N] = E;
    }
}

__global__ void scatter_kernel(const int* __restrict__ er, const int* __restrict__ ec,
                               const float* __restrict__ ev,
                               int* __restrict__ cur, int2* __restrict__ csr, int E) {
    int e = blockIdx.x * blockDim.x + threadIdx.x;
    if (e < E) {
        int pos = atomicAdd(&cur[er[e]], 1);
        csr[pos] = make_int2(ec[e], __float_as_int(ev[e]));
    }
}

// ---------------------------------------------------------------------------
// half2 gather helper: lane h owns 4 cols of the 64-col row -> one LDG.64
// ---------------------------------------------------------------------------
__device__ __forceinline__ void gather_fma_h(const __half* __restrict__ D,
                                             int col, int h, float v, float4& acc) {
    const uint2 u = *(reinterpret_cast<const uint2*>(D + (size_t)col * 64) + h);
    const __half2 p0 = *reinterpret_cast<const __half2*>(&u.x);
    const __half2 p1 = *reinterpret_cast<const __half2*>(&u.y);
    const float2 f0 = __half22float2(p0);
    const float2 f1 = __half22float2(p1);
    acc.x += v * f0.x; acc.y += v * f0.y;
    acc.z += v * f1.x; acc.w += v * f1.y;
}

// ---------------------------------------------------------------------------
// CSR SpMM, fp16 gather operand -> fp32 out: half-warp per row.
// ---------------------------------------------------------------------------
__global__ void csr_spmm_h_kernel(const int* __restrict__ ptr, const int2* __restrict__ csr,
                                  const __half* __restrict__ D, float* __restrict__ O, int N) {
    const int lane = threadIdx.x & 31;
    const int g = lane >> 4;
    const int h = lane & 15;
    const int warpId = (blockIdx.x * blockDim.x + threadIdx.x) >> 5;
    const int row = warpId * 2 + g;
    if (row >= N) return;

    const int start = ptr[row];
    const int end   = ptr[row + 1];

    float4 acc = make_float4(0.f, 0.f, 0.f, 0.f);
    int j = start;

    for (; j + 4 <= end; j += 4) {
        const int2 m0 = __ldg(&csr[j]);
        const int2 m1 = __ldg(&csr[j + 1]);
        const int2 m2 = __ldg(&csr[j + 2]);
        const int2 m3 = __ldg(&csr[j + 3]);
        gather_fma_h(D, m0.x, h, __int_as_float(m0.y), acc);
        gather_fma_h(D, m1.x, h, __int_as_float(m1.y), acc);
        gather_fma_h(D, m2.x, h, __int_as_float(m2.y), acc);
        gather_fma_h(D, m3.x, h, __int_as_float(m3.y), acc);
    }
    for (; j < end; j++) {
        const int2 m = __ldg(&csr[j]);
        gather_fma_h(D, m.x, h, __int_as_float(m.y), acc);
    }

    *(reinterpret_cast<float4*>(O + (size_t)row * 64) + h) = acc;
}

// ---------------------------------------------------------------------------
// Tiled GEMM (R4 scalar core), fp32 in -> fp16 out: C_h = act(X)@W + b
// ---------------------------------------------------------------------------
template<int K, bool RELU>
__global__ void gemm64_f16out_kernel(const float* __restrict__ X,
                                     const float* __restrict__ W,
                                     const float* __restrict__ b,
                                     __half* __restrict__ C, int N) {
    constexpr int BK = 32;
    __shared__ float Xs[64][BK + 1];
    __shared__ float Ws[BK][64];

    const int tid = threadIdx.x;
    const int tx = tid & 15;
    const int ty = tid >> 4;
    const int nodeBase = blockIdx.x * 64;

    float acc[4][4];
    const float4 bv = *reinterpret_cast<const float4*>(b + tx * 4);
#pragma unroll
    for (int i = 0; i < 4; i++) {
        acc[i][0] = bv.x; acc[i][1] = bv.y; acc[i][2] = bv.z; acc[i][3] = bv.w;
    }

    for (int kc = 0; kc < K; kc += BK) {
#pragma unroll
        for (int t = 0; t < 2; t++) {
            int idx = tid + t * 256;
            int r   = idx >> 3;
            int c4  = idx & 7;
            int node = nodeBase + r;
            float4 xv = make_float4(0.f, 0.f, 0.f, 0.f);
            if (node < N)
                xv = *reinterpret_cast<const float4*>(X + (size_t)node * K + kc + c4 * 4);
            if (RELU) {
                xv.x = fmaxf(xv.x, 0.f); xv.y = fmaxf(xv.y, 0.f);
                xv.z = fmaxf(xv.z, 0.f); xv.w = fmaxf(xv.w, 0.f);
            }
            Xs[r][c4 * 4 + 0] = xv.x;
            Xs[r][c4 * 4 + 1] = xv.y;
            Xs[r][c4 * 4 + 2] = xv.z;
            Xs[r][c4 * 4 + 3] = xv.w;
        }
#pragma unroll
        for (int t = 0; t < 2; t++) {
            int idx = tid + t * 256;
            int r   = idx >> 4;
            int c4  = idx & 15;
            *reinterpret_cast<float4*>(&Ws[r][c4 * 4]) =
                *reinterpret_cast<const float4*>(W + (size_t)(kc + r) * 64 + c4 * 4);
        }
        __syncthreads();

#pragma unroll
        for (int kk = 0; kk < BK; kk++) {
            const float4 wv = *reinterpret_cast<const float4*>(&Ws[kk][tx * 4]);
            float xv[4];
#pragma unroll
            for (int i = 0; i < 4; i++) xv[i] = Xs[ty * 4 + i][kk];
#pragma unroll
            for (int i = 0; i < 4; i++) {
                acc[i][0] += xv[i] * wv.x;
                acc[i][1] += xv[i] * wv.y;
                acc[i][2] += xv[i] * wv.z;
                acc[i][3] += xv[i] * wv.w;
            }
        }
        __syncthreads();
    }

#pragma unroll
    for (int i = 0; i < 4; i++) {
        int node = nodeBase + ty * 4 + i;
        if (node < N) {
            union { __half2 hh[2]; uint2 u; } pk;
            pk.hh[0] = __float22half2_rn(make_float2(acc[i][0], acc[i][1]));
            pk.hh[1] = __float22half2_rn(make_float2(acc[i][2], acc[i][3]));
            *reinterpret_cast<uint2*>(C + (size_t)node * 64 + tx * 4) = pk.u;
        }
    }
}

// ---------------------------------------------------------------------------
// Fused SpMM2 + classifier, fp16 gather operand (R10 structure otherwise)
// ---------------------------------------------------------------------------
__global__ void spmm_classifier_h_kernel(const int* __restrict__ ptr,
                                         const int2* __restrict__ csr,
                                         const __half* __restrict__ D,
                                         const float* __restrict__ Wc,
                                         const float* __restrict__ bc,
                                         float* __restrict__ out, int N) {
    __shared__ float  hs[16][64];
    __shared__ float2 Wp[64][32];
    __shared__ float  bs[40];

    const int tid  = threadIdx.x;
    const int lane = tid & 31;
    const int warp = tid >> 5;
    const int g = lane >> 4;
    const int h = lane & 15;

    for (int i = tid; i < 64 * 32; i += 256) {
        int k = i >> 5, l = i & 31;
        float w0 = Wc[k * 40 + l];
        float w1 = (l < 8) ? Wc[k * 40 + 32 + l] : 0.f;
        Wp[k][l] = make_float2(w0, w1);
    }
    if (tid < 40) bs[tid] = bc[tid];

    const int localRow = warp * 2 + g;
    const int row = blockIdx.x * 16 + localRow;

    if (row < N) {
        const int start = ptr[row];
        const int end   = ptr[row + 1];

        float4 acc = make_float4(0.f, 0.f, 0.f, 0.f);
        int j = start;

        for (; j + 4 <= end; j += 4) {
            const int2 m0 = __ldg(&csr[j]);
            const int2 m1 = __ldg(&csr[j + 1]);
            const int2 m2 = __ldg(&csr[j + 2]);
            const int2 m3 = __ldg(&csr[j + 3]);
            gather_fma_h(D, m0.x, h, __int_as_float(m0.y), acc);
            gather_fma_h(D, m1.x, h, __int_as_float(m1.y), acc);
            gather_fma_h(D, m2.x, h, __int_as_float(m2.y), acc);
            gather_fma_h(D, m3.x, h, __int_as_float(m3.y), acc);
        }
        for (; j < end; j++) {
            const int2 m = __ldg(&csr[j]);
            gather_fma_h(D, m.x, h, __int_as_float(m.y), acc);
        }

        *reinterpret_cast<float4*>(&hs[localRow][h * 4]) = acc;
    }
    __syncthreads();

#pragma unroll
    for (int it = 0; it < 2; it++) {
        const int r = warp * 2 + it;
        const int node = blockIdx.x * 16 + r;
        if (node < N) {
            float v0 = bs[lane];
            float v1 = (lane < 8) ? bs[32 + lane] : 0.f;
#pragma unroll
            for (int k = 0; k < 64; k++) {
                const float hv = hs[r][k];
                const float2 w = Wp[k][lane];
                v0 += hv * w.x;
                v1 += hv * w.y;
            }

            float m = (lane < 8) ? fmaxf(v0, v1) : v0;
#pragma unroll
            for (int off = 16; off; off >>= 1)
                m = fmaxf(m, __shfl_xor_sync(0xffffffffu, m, off));
            float s = expf(v0 - m) + ((lane < 8) ? expf(v1 - m) : 0.f);
#pragma unroll
            for (int off = 16; off; off >>= 1)
                s += __shfl_xor_sync(0xffffffffu, s, off);
            const float lse = m + logf(s);

            out[(size_t)node * 40 + lane] = v0 - lse;
            if (lane < 8)
                out[(size_t)node * 40 + 32 + lane] = v1 - lse;
        }
    }
}

// ---------------------------------------------------------------------------
// launch (single stream, R10 structure; fp16 support buffers)
// ---------------------------------------------------------------------------
extern "C" void kernel_launch(void* const* d_in, const int* in_sizes, int n_in,
                              void* d_out, int out_size) {
    const float* x  = (const float*)d_in[0];
    const int*   er = (const int*)  d_in[1];
    const int*   ec = (const int*)  d_in[2];
    const float* ev = (const float*)d_in[3];
    const float* W1 = (const float*)d_in[4];
    const float* b1 = (const float*)d_in[5];
    const float* W2 = (const float*)d_in[6];
    const float* b2 = (const float*)d_in[7];
    const float* Wc = (const float*)d_in[8];
    const float* bc = (const float*)d_in[9];
    float* out = (float*)d_out;

    const int N = in_sizes[0] / IN_DIM;   // 100000
    const int E = in_sizes[1];            // 1600000

    void *pH_, *pB_, *pCnt_, *pPtr_, *pPar_, *pCsr_;
    cudaGetSymbolAddress(&pH_, g_h);
    cudaGetSymbolAddress(&pB_, g_B);
    cudaGetSymbolAddress(&pCnt_, g_cnt);
    cudaGetSymbolAddress(&pPtr_, g_ptr);
    cudaGetSymbolAddress(&pPar_, g_partials);
    cudaGetSymbolAddress(&pCsr_, g_csr);
    __half* Hh  = (__half*)pH_;
    float*  B   = (float*)pB_;
    int*    cnt = (int*)pCnt_;
    int*    ptr = (int*)pPtr_;
    int*    par = (int*)pPar_;
    int2*   csr = (int2*)pCsr_;

    const int gemmBlocks = (N + 63) / 64;
    const int eBlocks    = (E + 255) / 256;
    const int spmmBlocks = (N + 15) / 16;

    // --- CSR build (block_scan = env marker at position 4) ---
    zero_int_kernel<<<(N + 255) / 256, 256>>>(cnt, N);
    hist_kernel<<<eBlocks, 256>>>(er, cnt, E);
    chunk_reduce_kernel<<<NCHUNK, CHUNK>>>(cnt, par, N);
    block_scan_kernel<<<NCHUNK, CHUNK>>>(cnt, par, ptr, cnt /*cursor*/, N, E);
    scatter_kernel<<<eBlocks, 256>>>(er, ec, ev, cnt, csr, E);

    // --- Layer 1: support1(fp16) = x@W1+b1 ; h1(fp32) = spmm(support1) ---
    gemm64_f16out_kernel<IN_DIM, false><<<gemmBlocks, 256>>>(x, W1, b1, Hh, N);
    csr_spmm_h_kernel<<<spmmBlocks, 256>>>(ptr, csr, Hh, B, N);

    // --- Layer 2: support2(fp16) = relu(h1)@W2+b2 (relu fused into read) ---
    gemm64_f16out_kernel<HID, true><<<gemmBlocks, 256>>>(B, W2, b2, Hh, N);

    // --- SpMM2 + classifier fused (fp16 gather) ---
    spmm_classifier_h_kernel<<<spmmBlocks, 256>>>(ptr, csr, Hh, Wc, bc, out, N);
}

// round 16
// speedup vs baseline: 1.2165x; 1.1521x over previous
#include <cuda_runtime.h>
#include <cuda_fp16.h>
#include <math.h>

#define N_NODES 100000
#define IN_DIM  128
#define HID     64
#define NCLS    40
#define N_EDGES 1600000
#define CHUNK   512
#define NCHUNK  ((N_NODES + CHUNK - 1) / CHUNK)   // 196

// Scratch (__device__ globals per alloc-free rule)
__device__ __half g_h[(size_t)N_NODES * HID];   // fp16 support buffer (layer1 then layer2)
__device__ float  g_B[(size_t)N_NODES * HID];   // fp32 h1 buffer
__device__ __half g_w1t[64 * IN_DIM];           // W1 transposed fp16 [n][k]
__device__ __half g_w2t[64 * HID];              // W2 transposed fp16 [n][k]
__device__ int    g_cnt[N_NODES];
__device__ int    g_ptr[N_NODES + 1];
__device__ int    g_partials[NCHUNK];
__device__ int2   g_csr[N_EDGES];

// ---------------------------------------------------------------------------
// fp16 MMA m16n8k16 (fp32 accumulate)
// ---------------------------------------------------------------------------
__device__ __forceinline__ void mma_f16(float4& d,
                                        unsigned a0, unsigned a1, unsigned a2, unsigned a3,
                                        unsigned b0, unsigned b1) {
    asm volatile(
        "mma.sync.aligned.m16n8k16.row.col.f32.f16.f16.f32 "
        "{%0,%1,%2,%3}, {%4,%5,%6,%7}, {%8,%9}, {%0,%1,%2,%3};"
        : "+f"(d.x), "+f"(d.y), "+f"(d.z), "+f"(d.w)
        : "r"(a0), "r"(a1), "r"(a2), "r"(a3), "r"(b0), "r"(b1));
}

// ---------------------------------------------------------------------------
// One-off: transpose + convert W1, W2 to fp16 [n][k]
// ---------------------------------------------------------------------------
__global__ void convert_wt_kernel(const float* __restrict__ W1,
                                  const float* __restrict__ W2,
                                  __half* __restrict__ W1t,
                                  __half* __restrict__ W2t) {
    int idx = blockIdx.x * blockDim.x + threadIdx.x;
    if (idx < IN_DIM * 64) {
        int k = idx / 64, n = idx % 64;
        W1t[n * IN_DIM + k] = __float2half(W1[idx]);
    }
    idx -= IN_DIM * 64;
    if (idx >= 0 && idx < HID * 64) {
        int k = idx / 64, n = idx % 64;
        W2t[n * HID + k] = __float2half(W2[idx]);
    }
}

// ---------------------------------------------------------------------------
// CSR construction (unchanged; block_scan at launch position 4 = env marker)
// ---------------------------------------------------------------------------
__global__ void zero_int_kernel(int* __restrict__ p, int n) {
    int i = blockIdx.x * blockDim.x + threadIdx.x;
    if (i < n) p[i] = 0;
}

__global__ void hist_kernel(const int* __restrict__ er, int* __restrict__ cnt, int E) {
    int e = blockIdx.x * blockDim.x + threadIdx.x;
    if (e < E) atomicAdd(&cnt[er[e]], 1);
}

__global__ void chunk_reduce_kernel(const int* __restrict__ cnt, int* __restrict__ partials, int N) {
    __shared__ int s[CHUNK];
    int t = threadIdx.x;
    int i = blockIdx.x * CHUNK + t;
    s[t] = (i < N) ? cnt[i] : 0;
    __syncthreads();
    for (int off = CHUNK / 2; off > 0; off >>= 1) {
        if (t < off) s[t] += s[t + off];
        __syncthreads();
    }
    if (t == 0) partials[blockIdx.x] = s[0];
}

__global__ void block_scan_kernel(const int* __restrict__ cnt,
                                  const int* __restrict__ partials,
                                  int* __restrict__ ptr, int* __restrict__ cur,
                                  int N, int E) {
    __shared__ int s[CHUNK];
    __shared__ int p[256];
    int t = threadIdx.x;

    if (t < 256) p[t] = (t < NCHUNK) ? partials[t] : 0;
    __syncthreads();
#pragma unroll
    for (int off = 1; off < 256; off <<= 1) {
        int x = (t < 256 && t >= off) ? p[t - off] : 0;
        __syncthreads();
        if (t < 256) p[t] += x;
        __syncthreads();
    }
    const int chunkOff = (blockIdx.x == 0) ? 0 : p[blockIdx.x - 1];

    int i = blockIdx.x * CHUNK + t;
    int c = (i < N) ? cnt[i] : 0;
    s[t] = c;
    __syncthreads();
#pragma unroll
    for (int off = 1; off < CHUNK; off <<= 1) {
        int x = (t >= off) ? s[t - off] : 0;
        __syncthreads();
        s[t] += x;
        __syncthreads();
    }
    if (i < N) {
        int start = chunkOff + s[t] - c;
        ptr[i] = start;
        cur[i] = start;
        if (i == N - 1) ptr[N] = E;
    }
}

__global__ void scatter_kernel(const int* __restrict__ er, const int* __restrict__ ec,
                               const float* __restrict__ ev,
                               int* __restrict__ cur, int2* __restrict__ csr, int E) {
    int e = blockIdx.x * blockDim.x + threadIdx.x;
    if (e < E) {
        int pos = atomicAdd(&cur[er[e]], 1);
        csr[pos] = make_int2(ec[e], __float_as_int(ev[e]));
    }
}

// ---------------------------------------------------------------------------
// half2 gather helper (R15)
// ---------------------------------------------------------------------------
__device__ __forceinline__ void gather_fma_h(const __half* __restrict__ D,
                                             int col, int h, float v, float4& acc) {
    const uint2 u = *(reinterpret_cast<const uint2*>(D + (size_t)col * 64) + h);
    const __half2 p0 = *reinterpret_cast<const __half2*>(&u.x);
    const __half2 p1 = *reinterpret_cast<const __half2*>(&u.y);
    const float2 f0 = __half22float2(p0);
    const float2 f1 = __half22float2(p1);
    acc.x += v * f0.x; acc.y += v * f0.y;
    acc.z += v * f1.x; acc.w += v * f1.y;
}

// ---------------------------------------------------------------------------
// CSR SpMM, fp16 gather -> fp32 out (R15, unchanged)
// ---------------------------------------------------------------------------
__global__ void csr_spmm_h_kernel(const int* __restrict__ ptr, const int2* __restrict__ csr,
                                  const __half* __restrict__ D, float* __restrict__ O, int N) {
    const int lane = threadIdx.x & 31;
    const int g = lane >> 4;
    const int h = lane & 15;
    const int warpId = (blockIdx.x * blockDim.x + threadIdx.x) >> 5;
    const int row = warpId * 2 + g;
    if (row >= N) return;

    const int start = ptr[row];
    const int end   = ptr[row + 1];

    float4 acc = make_float4(0.f, 0.f, 0.f, 0.f);
    int j = start;

    for (; j + 4 <= end; j += 4) {
        const int2 m0 = __ldg(&csr[j]);
        const int2 m1 = __ldg(&csr[j + 1]);
        const int2 m2 = __ldg(&csr[j + 2]);
        const int2 m3 = __ldg(&csr[j + 3]);
        gather_fma_h(D, m0.x, h, __int_as_float(m0.y), acc);
        gather_fma_h(D, m1.x, h, __int_as_float(m1.y), acc);
        gather_fma_h(D, m2.x, h, __int_as_float(m2.y), acc);
        gather_fma_h(D, m3.x, h, __int_as_float(m3.y), acc);
    }
    for (; j < end; j++) {
        const int2 m = __ldg(&csr[j]);
        gather_fma_h(D, m.x, h, __int_as_float(m.y), acc);
    }

    *(reinterpret_cast<float4*>(O + (size_t)row * 64) + h) = acc;
}

// ---------------------------------------------------------------------------
// fp16 tensor-core GEMM: C_h[N,64] = act(X[N,K]) @ W[K,64] + b
// 64x64 tile, 256 threads = 8 warps (4 M x 2 N); m16n8k16, fp32 accumulate.
// Xs/Wt smem strides (K+8 halfs) make all fragment LDS bank-conflict-free:
//   bank = (4*qr + qc + const) mod 32, a bijection over the warp.
// ---------------------------------------------------------------------------
template<int K, bool RELU>
__global__ void gemm_f16mma_kernel(const float* __restrict__ X,
                                   const __half* __restrict__ Wt,   // [64][K]
                                   const float* __restrict__ b,
                                   __half* __restrict__ C, int N) {
    constexpr int KS = K + 8;                     // smem stride in halfs
    __shared__ __half Xs[64 * KS];
    __shared__ __half Ws[64 * KS];
    __shared__ float  bsm[64];

    const int tid  = threadIdx.x;
    const int lane = tid & 31;
    const int warp = tid >> 5;
    const int mw = warp & 3;                      // M-warp: rows mw*16..+15
    const int nw = warp >> 2;                     // N-warp: cols nw*32..+31
    const int qr = lane >> 2;                     // 0..7
    const int qc = lane & 3;                      // 0..3
    const int nodeBase = blockIdx.x * 64;

    if (tid < 64) bsm[tid] = b[tid];

    // Load X tile (fp32 -> fp16), 64 rows x K cols, coalesced float4.
    for (int idx = tid; idx < 64 * (K / 4); idx += 256) {
        const int r  = idx / (K / 4);
        const int c4 = idx % (K / 4);
        const int node = nodeBase + r;
        float4 xv = make_float4(0.f, 0.f, 0.f, 0.f);
        if (node < N)
            xv = *reinterpret_cast<const float4*>(X + (size_t)node * K + c4 * 4);
        if (RELU) {
            xv.x = fmaxf(xv.x, 0.f); xv.y = fmaxf(xv.y, 0.f);
            xv.z = fmaxf(xv.z, 0.f); xv.w = fmaxf(xv.w, 0.f);
        }
        union { __half2 hh[2]; uint2 u; } pk;
        pk.hh[0] = __float22half2_rn(make_float2(xv.x, xv.y));
        pk.hh[1] = __float22half2_rn(make_float2(xv.z, xv.w));
        *reinterpret_cast<uint2*>(&Xs[r * KS + c4 * 4]) = pk.u;
    }
    // Load Wt (fp16, [64][K] contiguous) via uint4 (8 halfs).
    for (int idx = tid; idx < 64 * (K / 8); idx += 256) {
        const int n  = idx / (K / 8);
        const int k8 = idx % (K / 8);
        *reinterpret_cast<uint4*>(&Ws[n * KS + k8 * 8]) =
            *reinterpret_cast<const uint4*>(Wt + (size_t)n * K + k8 * 8);
    }
    __syncthreads();

    // Accumulators: 4 n-groups of 8 cols each; init with bias.
    float4 acc[4];
#pragma unroll
    for (int s = 0; s < 4; s++) {
        const int col0 = nw * 32 + s * 8 + 2 * qc;
        acc[s].x = bsm[col0];     acc[s].y = bsm[col0 + 1];
        acc[s].z = bsm[col0];     acc[s].w = bsm[col0 + 1];
    }

    const __half* xrow0 = &Xs[(mw * 16 + qr) * KS];
    const __half* xrow1 = &Xs[(mw * 16 + qr + 8) * KS];

#pragma unroll
    for (int kk = 0; kk < K / 16; kk++) {
        const int k0 = kk * 16;
        const unsigned a0 = *reinterpret_cast<const unsigned*>(xrow0 + k0 + 2 * qc);
        const unsigned a1 = *reinterpret_cast<const unsigned*>(xrow1 + k0 + 2 * qc);
        const unsigned a2 = *reinterpret_cast<const unsigned*>(xrow0 + k0 + 8 + 2 * qc);
        const unsigned a3 = *reinterpret_cast<const unsigned*>(xrow1 + k0 + 8 + 2 * qc);
#pragma unroll
        for (int s = 0; s < 4; s++) {
            const int n0 = nw * 32 + s * 8;
            const __half* wrow = &Ws[(n0 + qr) * KS];
            const unsigned b0 = *reinterpret_cast<const unsigned*>(wrow + k0 + 2 * qc);
            const unsigned b1 = *reinterpret_cast<const unsigned*>(wrow + k0 + 8 + 2 * qc);
            mma_f16(acc[s], a0, a1, a2, a3, b0, b1);
        }
    }

    // Epilogue: fp16 store. c0,c1 -> row0; c2,c3 -> row0+8.
    const int row0 = nodeBase + mw * 16 + qr;
    const int row1 = row0 + 8;
#pragma unroll
    for (int s = 0; s < 4; s++) {
        const int col0 = nw * 32 + s * 8 + 2 * qc;
        if (row0 < N) {
            const __half2 h0 = __float22half2_rn(make_float2(acc[s].x, acc[s].y));
            *reinterpret_cast<__half2*>(C + (size_t)row0 * 64 + col0) = h0;
        }
        if (row1 < N) {
            const __half2 h1 = __float22half2_rn(make_float2(acc[s].z, acc[s].w));
            *reinterpret_cast<__half2*>(C + (size_t)row1 * 64 + col0) = h1;
        }
    }
}

// ---------------------------------------------------------------------------
// Fused SpMM2 + classifier, fp16 gather (R15, unchanged)
// ---------------------------------------------------------------------------
__global__ void spmm_classifier_h_kernel(const int* __restrict__ ptr,
                                         const int2* __restrict__ csr,
                                         const __half* __restrict__ D,
                                         const float* __restrict__ Wc,
                                         const float* __restrict__ bc,
                                         float* __restrict__ out, int N) {
    __shared__ float  hs[16][64];
    __shared__ float2 Wp[64][32];
    __shared__ float  bs[40];

    const int tid  = threadIdx.x;
    const int lane = tid & 31;
    const int warp = tid >> 5;
    const int g = lane >> 4;
    const int h = lane & 15;

    for (int i = tid; i < 64 * 32; i += 256) {
        int k = i >> 5, l = i & 31;
        float w0 = Wc[k * 40 + l];
        float w1 = (l < 8) ? Wc[k * 40 + 32 + l] : 0.f;
        Wp[k][l] = make_float2(w0, w1);
    }
    if (tid < 40) bs[tid] = bc[tid];

    const int localRow = warp * 2 + g;
    const int row = blockIdx.x * 16 + localRow;

    if (row < N) {
        const int start = ptr[row];
        const int end   = ptr[row + 1];

        float4 acc = make_float4(0.f, 0.f, 0.f, 0.f);
        int j = start;

        for (; j + 4 <= end; j += 4) {
            const int2 m0 = __ldg(&csr[j]);
            const int2 m1 = __ldg(&csr[j + 1]);
            const int2 m2 = __ldg(&csr[j + 2]);
            const int2 m3 = __ldg(&csr[j + 3]);
            gather_fma_h(D, m0.x, h, __int_as_float(m0.y), acc);
            gather_fma_h(D, m1.x, h, __int_as_float(m1.y), acc);
            gather_fma_h(D, m2.x, h, __int_as_float(m2.y), acc);
            gather_fma_h(D, m3.x, h, __int_as_float(m3.y), acc);
        }
        for (; j < end; j++) {
            const int2 m = __ldg(&csr[j]);
            gather_fma_h(D, m.x, h, __int_as_float(m.y), acc);
        }

        *reinterpret_cast<float4*>(&hs[localRow][h * 4]) = acc;
    }
    __syncthreads();

#pragma unroll
    for (int it = 0; it < 2; it++) {
        const int r = warp * 2 + it;
        const int node = blockIdx.x * 16 + r;
        if (node < N) {
            float v0 = bs[lane];
            float v1 = (lane < 8) ? bs[32 + lane] : 0.f;
#pragma unroll
            for (int k = 0; k < 64; k++) {
                const float hv = hs[r][k];
                const float2 w = Wp[k][lane];
                v0 += hv * w.x;
                v1 += hv * w.y;
            }

            float m = (lane < 8) ? fmaxf(v0, v1) : v0;
#pragma unroll
            for (int off = 16; off; off >>= 1)
                m = fmaxf(m, __shfl_xor_sync(0xffffffffu, m, off));
            float s = expf(v0 - m) + ((lane < 8) ? expf(v1 - m) : 0.f);
#pragma unroll
            for (int off = 16; off; off >>= 1)
                s += __shfl_xor_sync(0xffffffffu, s, off);
            const float lse = m + logf(s);

            out[(size_t)node * 40 + lane] = v0 - lse;
            if (lane < 8)
                out[(size_t)node * 40 + 32 + lane] = v1 - lse;
        }
    }
}

// ---------------------------------------------------------------------------
// launch (single stream; block_scan at position 4 = env marker)
// ---------------------------------------------------------------------------
extern "C" void kernel_launch(void* const* d_in, const int* in_sizes, int n_in,
                              void* d_out, int out_size) {
    const float* x  = (const float*)d_in[0];
    const int*   er = (const int*)  d_in[1];
    const int*   ec = (const int*)  d_in[2];
    const float* ev = (const float*)d_in[3];
    const float* W1 = (const float*)d_in[4];
    const float* b1 = (const float*)d_in[5];
    const float* W2 = (const float*)d_in[6];
    const float* b2 = (const float*)d_in[7];
    const float* Wc = (const float*)d_in[8];
    const float* bc = (const float*)d_in[9];
    float* out = (float*)d_out;

    const int N = in_sizes[0] / IN_DIM;   // 100000
    const int E = in_sizes[1];            // 1600000

    void *pH_, *pB_, *pW1t_, *pW2t_, *pCnt_, *pPtr_, *pPar_, *pCsr_;
    cudaGetSymbolAddress(&pH_, g_h);
    cudaGetSymbolAddress(&pB_, g_B);
    cudaGetSymbolAddress(&pW1t_, g_w1t);
    cudaGetSymbolAddress(&pW2t_, g_w2t);
    cudaGetSymbolAddress(&pCnt_, g_cnt);
    cudaGetSymbolAddress(&pPtr_, g_ptr);
    cudaGetSymbolAddress(&pPar_, g_partials);
    cudaGetSymbolAddress(&pCsr_, g_csr);
    __half* Hh   = (__half*)pH_;
    float*  B    = (float*)pB_;
    __half* W1t  = (__half*)pW1t_;
    __half* W2t  = (__half*)pW2t_;
    int*    cnt  = (int*)pCnt_;
    int*    ptr  = (int*)pPtr_;
    int*    par  = (int*)pPar_;
    int2*   csr  = (int2*)pCsr_;

    const int gemmBlocks = (N + 63) / 64;
    const int eBlocks    = (E + 255) / 256;
    const int spmmBlocks = (N + 15) / 16;

    // --- CSR build (block_scan = env marker at position 4) ---
    zero_int_kernel<<<(N + 255) / 256, 256>>>(cnt, N);
    hist_kernel<<<eBlocks, 256>>>(er, cnt, E);
    chunk_reduce_kernel<<<NCHUNK, CHUNK>>>(cnt, par, N);
    block_scan_kernel<<<NCHUNK, CHUNK>>>(cnt, par, ptr, cnt /*cursor*/, N, E);
    scatter_kernel<<<eBlocks, 256>>>(er, ec, ev, cnt, csr, E);

    // --- One-off weight transpose/convert (tiny) ---
    convert_wt_kernel<<<((IN_DIM + HID) * 64 + 255) / 256, 256>>>(W1, W2, W1t, W2t);

    // --- Layer 1: support1(fp16) = x@W1+b1 (tensor cores); h1 = spmm ---
    gemm_f16mma_kernel<IN_DIM, false><<<gemmBlocks, 256>>>(x, W1t, b1, Hh, N);
    csr_spmm_h_kernel<<<spmmBlocks, 256>>>(ptr, csr, Hh, B, N);

    // --- Layer 2: support2(fp16) = relu(h1)@W2+b2 (tensor cores) ---
    gemm_f16mma_kernel<HID, true><<<gemmBlocks, 256>>>(B, W2t, b2, Hh, N);

    // --- SpMM2 + classifier fused (fp16 gather) ---
    spmm_classifier_h_kernel<<<spmmBlocks, 256>>>(ptr, csr, Hh, Wc, bc, out, N);
}

// round 17
// speedup vs baseline: 1.6896x; 1.3890x over previous
#include <cuda_runtime.h>
#include <cuda_fp16.h>
#include <math.h>

#define N_NODES 100000
#define IN_DIM  128
#define HID     64
#define NCLS    40
#define N_EDGES 1600000
#define CHUNK   512
#define NCHUNK  ((N_NODES + CHUNK - 1) / CHUNK)   // 196

// Scratch (__device__ globals per alloc-free rule)
__device__ __half g_h[(size_t)N_NODES * HID];    // fp16 support buffer (layer1 then layer2)
__device__ __half g_h2[(size_t)N_NODES * HID];   // fp16 h2 buffer
__device__ float  g_B[(size_t)N_NODES * HID];    // fp32 h1 buffer
__device__ __half g_w1t[64 * IN_DIM];            // W1^T fp16 [n][k]
__device__ __half g_w2t[64 * HID];               // W2^T fp16 [n][k]
__device__ __half g_wct[48 * HID];               // Wc^T fp16 [n][k], rows 40-47 zero
__device__ int    g_cnt[N_NODES];
__device__ int    g_ptr[N_NODES + 1];
__device__ int    g_partials[NCHUNK];
__device__ int2   g_csr[N_EDGES];

// ---------------------------------------------------------------------------
// fp16 MMA m16n8k16 (fp32 accumulate)
// ---------------------------------------------------------------------------
__device__ __forceinline__ void mma_f16(float4& d,
                                        unsigned a0, unsigned a1, unsigned a2, unsigned a3,
                                        unsigned b0, unsigned b1) {
    asm volatile(
        "mma.sync.aligned.m16n8k16.row.col.f32.f16.f16.f32 "
        "{%0,%1,%2,%3}, {%4,%5,%6,%7}, {%8,%9}, {%0,%1,%2,%3};"
        : "+f"(d.x), "+f"(d.y), "+f"(d.z), "+f"(d.w)
        : "r"(a0), "r"(a1), "r"(a2), "r"(a3), "r"(b0), "r"(b1));
}

// ---------------------------------------------------------------------------
// One-off: transpose + convert W1, W2, Wc to fp16 [n][k]
// ---------------------------------------------------------------------------
__global__ void convert_wt_kernel(const float* __restrict__ W1,
                                  const float* __restrict__ W2,
                                  const float* __restrict__ Wc,
                                  __half* __restrict__ W1t,
                                  __half* __restrict__ W2t,
                                  __half* __restrict__ Wct) {
    int idx = blockIdx.x * blockDim.x + threadIdx.x;
    if (idx < IN_DIM * 64) {
        int k = idx / 64, n = idx % 64;
        W1t[n * IN_DIM + k] = __float2half(W1[idx]);
        return;
    }
    idx -= IN_DIM * 64;
    if (idx < HID * 64) {
        int k = idx / 64, n = idx % 64;
        W2t[n * HID + k] = __float2half(W2[idx]);
        return;
    }
    idx -= HID * 64;
    if (idx < 48 * HID) {
        int n = idx / HID, k = idx % HID;
        Wct[n * HID + k] = (n < NCLS) ? __float2half(Wc[k * NCLS + n]) : __float2half(0.f);
    }
}

// ---------------------------------------------------------------------------
// CSR construction (unchanged; block_scan at launch position 4 = env marker)
// ---------------------------------------------------------------------------
__global__ void zero_int_kernel(int* __restrict__ p, int n) {
    int i = blockIdx.x * blockDim.x + threadIdx.x;
    if (i < n) p[i] = 0;
}

__global__ void hist_kernel(const int* __restrict__ er, int* __restrict__ cnt, int E) {
    int e = blockIdx.x * blockDim.x + threadIdx.x;
    if (e < E) atomicAdd(&cnt[er[e]], 1);
}

__global__ void chunk_reduce_kernel(const int* __restrict__ cnt, int* __restrict__ partials, int N) {
    __shared__ int s[CHUNK];
    int t = threadIdx.x;
    int i = blockIdx.x * CHUNK + t;
    s[t] = (i < N) ? cnt[i] : 0;
    __syncthreads();
    for (int off = CHUNK / 2; off > 0; off >>= 1) {
        if (t < off) s[t] += s[t + off];
        __syncthreads();
    }
    if (t == 0) partials[blockIdx.x] = s[0];
}

__global__ void block_scan_kernel(const int* __restrict__ cnt,
                                  const int* __restrict__ partials,
                                  int* __restrict__ ptr, int* __restrict__ cur,
                                  int N, int E) {
    __shared__ int s[CHUNK];
    __shared__ int p[256];
    int t = threadIdx.x;

    if (t < 256) p[t] = (t < NCHUNK) ? partials[t] : 0;
    __syncthreads();
#pragma unroll
    for (int off = 1; off < 256; off <<= 1) {
        int x = (t < 256 && t >= off) ? p[t - off] : 0;
        __syncthreads();
        if (t < 256) p[t] += x;
        __syncthreads();
    }
    const int chunkOff = (blockIdx.x == 0) ? 0 : p[blockIdx.x - 1];

    int i = blockIdx.x * CHUNK + t;
    int c = (i < N) ? cnt[i] : 0;
    s[t] = c;
    __syncthreads();
#pragma unroll
    for (int off = 1; off < CHUNK; off <<= 1) {
        int x = (t >= off) ? s[t - off] : 0;
        __syncthreads();
        s[t] += x;
        __syncthreads();
    }
    if (i < N) {
        int start = chunkOff + s[t] - c;
        ptr[i] = start;
        cur[i] = start;
        if (i == N - 1) ptr[N] = E;
    }
}

__global__ void scatter_kernel(const int* __restrict__ er, const int* __restrict__ ec,
                               const float* __restrict__ ev,
                               int* __restrict__ cur, int2* __restrict__ csr, int E) {
    int e = blockIdx.x * blockDim.x + threadIdx.x;
    if (e < E) {
        int pos = atomicAdd(&cur[er[e]], 1);
        csr[pos] = make_int2(ec[e], __float_as_int(ev[e]));
    }
}

// ---------------------------------------------------------------------------
// Quarter-warp gather helper: lane h8 owns 8 cols (16B LDG.128) of a 64-col row
// ---------------------------------------------------------------------------
__device__ __forceinline__ void gacc8(const __half* __restrict__ D,
                                      int col, int h8, float v, float* acc) {
    const uint4 u = *(reinterpret_cast<const uint4*>(D + (size_t)col * 64) + h8);
    const __half2* p = reinterpret_cast<const __half2*>(&u);
#pragma unroll
    for (int i = 0; i < 4; i++) {
        const float2 f = __half22float2(p[i]);
        acc[2 * i]     += v * f.x;
        acc[2 * i + 1] += v * f.y;
    }
}

// ---------------------------------------------------------------------------
// CSR SpMM, quarter-warp per row (4 rows/warp), fp16 gather -> fp32 out
// ---------------------------------------------------------------------------
__global__ void csr_spmm_h2f_kernel(const int* __restrict__ ptr, const int2* __restrict__ csr,
                                    const __half* __restrict__ D, float* __restrict__ O, int N) {
    const int lane = threadIdx.x & 31;
    const int q  = lane >> 3;           // quarter 0..3 (row select)
    const int h8 = lane & 7;            // 16B chunk within row
    const int warpId = (blockIdx.x * blockDim.x + threadIdx.x) >> 5;
    const int row = warpId * 4 + q;
    if (row >= N) return;

    const int start = ptr[row];
    const int end   = ptr[row + 1];

    float acc[8];
#pragma unroll
    for (int i = 0; i < 8; i++) acc[i] = 0.f;

    int j = start;
    for (; j + 4 <= end; j += 4) {
        const int2 m0 = __ldg(&csr[j]);
        const int2 m1 = __ldg(&csr[j + 1]);
        const int2 m2 = __ldg(&csr[j + 2]);
        const int2 m3 = __ldg(&csr[j + 3]);
        gacc8(D, m0.x, h8, __int_as_float(m0.y), acc);
        gacc8(D, m1.x, h8, __int_as_float(m1.y), acc);
        gacc8(D, m2.x, h8, __int_as_float(m2.y), acc);
        gacc8(D, m3.x, h8, __int_as_float(m3.y), acc);
    }
    for (; j < end; j++) {
        const int2 m = __ldg(&csr[j]);
        gacc8(D, m.x, h8, __int_as_float(m.y), acc);
    }

    float4* dst = reinterpret_cast<float4*>(O + (size_t)row * 64 + h8 * 8);
    dst[0] = make_float4(acc[0], acc[1], acc[2], acc[3]);
    dst[1] = make_float4(acc[4], acc[5], acc[6], acc[7]);
}

// ---------------------------------------------------------------------------
// CSR SpMM, quarter-warp per row, fp16 gather -> fp16 out
// ---------------------------------------------------------------------------
__global__ void csr_spmm_h2h_kernel(const int* __restrict__ ptr, const int2* __restrict__ csr,
                                    const __half* __restrict__ D, __half* __restrict__ O, int N) {
    const int lane = threadIdx.x & 31;
    const int q  = lane >> 3;
    const int h8 = lane & 7;
    const int warpId = (blockIdx.x * blockDim.x + threadIdx.x) >> 5;
    const int row = warpId * 4 + q;
    if (row >= N) return;

    const int start = ptr[row];
    const int end   = ptr[row + 1];

    float acc[8];
#pragma unroll
    for (int i = 0; i < 8; i++) acc[i] = 0.f;

    int j = start;
    for (; j + 4 <= end; j += 4) {
        const int2 m0 = __ldg(&csr[j]);
        const int2 m1 = __ldg(&csr[j + 1]);
        const int2 m2 = __ldg(&csr[j + 2]);
        const int2 m3 = __ldg(&csr[j + 3]);
        gacc8(D, m0.x, h8, __int_as_float(m0.y), acc);
        gacc8(D, m1.x, h8, __int_as_float(m1.y), acc);
        gacc8(D, m2.x, h8, __int_as_float(m2.y), acc);
        gacc8(D, m3.x, h8, __int_as_float(m3.y), acc);
    }
    for (; j < end; j++) {
        const int2 m = __ldg(&csr[j]);
        gacc8(D, m.x, h8, __int_as_float(m.y), acc);
    }

    union { __half2 hh[4]; uint4 u; } pk;
#pragma unroll
    for (int i = 0; i < 4; i++)
        pk.hh[i] = __float22half2_rn(make_float2(acc[2 * i], acc[2 * i + 1]));
    *(reinterpret_cast<uint4*>(O + (size_t)row * 64) + h8) = pk.u;
}

// ---------------------------------------------------------------------------
// fp16 tensor-core GEMM (R16, unchanged): C_h = act(X)@W + b
// ---------------------------------------------------------------------------
template<int K, bool RELU>
__global__ void gemm_f16mma_kernel(const float* __restrict__ X,
                                   const __half* __restrict__ Wt,   // [64][K]
                                   const float* __restrict__ b,
                                   __half* __restrict__ C, int N) {
    constexpr int KS = K + 8;
    __shared__ __half Xs[64 * KS];
    __shared__ __half Ws[64 * KS];
    __shared__ float  bsm[64];

    const int tid  = threadIdx.x;
    const int lane = tid & 31;
    const int warp = tid >> 5;
    const int mw = warp & 3;
    const int nw = warp >> 2;
    const int qr = lane >> 2;
    const int qc = lane & 3;
    const int nodeBase = blockIdx.x * 64;

    if (tid < 64) bsm[tid] = b[tid];

    for (int idx = tid; idx < 64 * (K / 4); idx += 256) {
        const int r  = idx / (K / 4);
        const int c4 = idx % (K / 4);
        const int node = nodeBase + r;
        float4 xv = make_float4(0.f, 0.f, 0.f, 0.f);
        if (node < N)
            xv = *reinterpret_cast<const float4*>(X + (size_t)node * K + c4 * 4);
        if (RELU) {
            xv.x = fmaxf(xv.x, 0.f); xv.y = fmaxf(xv.y, 0.f);
            xv.z = fmaxf(xv.z, 0.f); xv.w = fmaxf(xv.w, 0.f);
        }
        union { __half2 hh[2]; uint2 u; } pk;
        pk.hh[0] = __float22half2_rn(make_float2(xv.x, xv.y));
        pk.hh[1] = __float22half2_rn(make_float2(xv.z, xv.w));
        *reinterpret_cast<uint2*>(&Xs[r * KS + c4 * 4]) = pk.u;
    }
    for (int idx = tid; idx < 64 * (K / 8); idx += 256) {
        const int n  = idx / (K / 8);
        const int k8 = idx % (K / 8);
        *reinterpret_cast<uint4*>(&Ws[n * KS + k8 * 8]) =
            *reinterpret_cast<const uint4*>(Wt + (size_t)n * K + k8 * 8);
    }
    __syncthreads();

    float4 acc[4];
#pragma unroll
    for (int s = 0; s < 4; s++) {
        const int col0 = nw * 32 + s * 8 + 2 * qc;
        acc[s].x = bsm[col0];     acc[s].y = bsm[col0 + 1];
        acc[s].z = bsm[col0];     acc[s].w = bsm[col0 + 1];
    }

    const __half* xrow0 = &Xs[(mw * 16 + qr) * KS];
    const __half* xrow1 = &Xs[(mw * 16 + qr + 8) * KS];

#pragma unroll
    for (int kk = 0; kk < K / 16; kk++) {
        const int k0 = kk * 16;
        const unsigned a0 = *reinterpret_cast<const unsigned*>(xrow0 + k0 + 2 * qc);
        const unsigned a1 = *reinterpret_cast<const unsigned*>(xrow1 + k0 + 2 * qc);
        const unsigned a2 = *reinterpret_cast<const unsigned*>(xrow0 + k0 + 8 + 2 * qc);
        const unsigned a3 = *reinterpret_cast<const unsigned*>(xrow1 + k0 + 8 + 2 * qc);
#pragma unroll
        for (int s = 0; s < 4; s++) {
            const int n0 = nw * 32 + s * 8;
            const __half* wrow = &Ws[(n0 + qr) * KS];
            const unsigned b0 = *reinterpret_cast<const unsigned*>(wrow + k0 + 2 * qc);
            const unsigned b1 = *reinterpret_cast<const unsigned*>(wrow + k0 + 8 + 2 * qc);
            mma_f16(acc[s], a0, a1, a2, a3, b0, b1);
        }
    }

    const int row0 = nodeBase + mw * 16 + qr;
    const int row1 = row0 + 8;
#pragma unroll
    for (int s = 0; s < 4; s++) {
        const int col0 = nw * 32 + s * 8 + 2 * qc;
        if (row0 < N) {
            const __half2 h0 = __float22half2_rn(make_float2(acc[s].x, acc[s].y));
            *reinterpret_cast<__half2*>(C + (size_t)row0 * 64 + col0) = h0;
        }
        if (row1 < N) {
            const __half2 h1 = __float22half2_rn(make_float2(acc[s].z, acc[s].w));
            *reinterpret_cast<__half2*>(C + (size_t)row1 * 64 + col0) = h1;
        }
    }
}

// ---------------------------------------------------------------------------
// Classifier via fp16 MMA: out = log_softmax(h2 @ Wc + bc)
// 64 nodes/block, 8 warps (4 M x 2 N-halves); N padded 40->48.
// Logits -> smem -> warp-softmax (proven R10 pattern).
// ---------------------------------------------------------------------------
__global__ void classifier_mma_kernel(const __half* __restrict__ H2,
                                      const __half* __restrict__ Wct,  // [48][64], rows 40+ zero
                                      const float* __restrict__ bc,
                                      float* __restrict__ out, int N) {
    constexpr int KS = HID + 8;   // 72
    __shared__ __half Hs[64 * KS];
    __shared__ __half Ws[48 * KS];
    __shared__ float  ls[64][52];
    __shared__ float  bs[40];

    const int tid  = threadIdx.x;
    const int lane = tid & 31;
    const int warp = tid >> 5;
    const int mw = warp & 3;
    const int nw = warp >> 2;       // 0: cols 0-23, 1: cols 24-47
    const int qr = lane >> 2;
    const int qc = lane & 3;
    const int nodeBase = blockIdx.x * 64;

    if (tid < 40) bs[tid] = bc[tid];

    // Load h2 tile (fp16, uint4 = 8 halfs)
    for (int idx = tid; idx < 64 * 8; idx += 256) {
        const int r  = idx >> 3;
        const int k8 = idx & 7;
        const int node = nodeBase + r;
        uint4 u = make_uint4(0u, 0u, 0u, 0u);
        if (node < N)
            u = *(reinterpret_cast<const uint4*>(H2 + (size_t)node * 64) + k8);
        *reinterpret_cast<uint4*>(&Hs[r * KS + k8 * 8]) = u;
    }
    // Load Wct (48 x 64)
    for (int idx = tid; idx < 48 * 8; idx += 256) {
        const int n  = idx >> 3;
        const int k8 = idx & 7;
        *reinterpret_cast<uint4*>(&Ws[n * KS + k8 * 8]) =
            *(reinterpret_cast<const uint4*>(Wct + (size_t)n * 64) + k8);
    }
    __syncthreads();

    float4 acc[3];
#pragma unroll
    for (int s = 0; s < 3; s++) {
        const int col0 = nw * 24 + s * 8 + 2 * qc;
        const float b0v = (col0 < 40) ? bs[col0] : 0.f;
        const float b1v = (col0 + 1 < 40) ? bs[col0 + 1] : 0.f;
        acc[s].x = b0v; acc[s].y = b1v;
        acc[s].z = b0v; acc[s].w = b1v;
    }

    const __half* xrow0 = &Hs[(mw * 16 + qr) * KS];
    const __half* xrow1 = &Hs[(mw * 16 + qr + 8) * KS];

#pragma unroll
    for (int kk = 0; kk < HID / 16; kk++) {
        const int k0 = kk * 16;
        const unsigned a0 = *reinterpret_cast<const unsigned*>(xrow0 + k0 + 2 * qc);
        const unsigned a1 = *reinterpret_cast<const unsigned*>(xrow1 + k0 + 2 * qc);
        const unsigned a2 = *reinterpret_cast<const unsigned*>(xrow0 + k0 + 8 + 2 * qc);
        const unsigned a3 = *reinterpret_cast<const unsigned*>(xrow1 + k0 + 8 + 2 * qc);
#pragma unroll
        for (int s = 0; s < 3; s++) {
            const int n0 = nw * 24 + s * 8;
            const __half* wrow = &Ws[(n0 + qr) * KS];
            const unsigned b0 = *reinterpret_cast<const unsigned*>(wrow + k0 + 2 * qc);
            const unsigned b1 = *reinterpret_cast<const unsigned*>(wrow + k0 + 8 + 2 * qc);
            mma_f16(acc[s], a0, a1, a2, a3, b0, b1);
        }
    }

    // Write logits to smem (cols >= 40 discarded)
    const int r0 = mw * 16 + qr;
    const int r1 = r0 + 8;
#pragma unroll
    for (int s = 0; s < 3; s++) {
        const int col0 = nw * 24 + s * 8 + 2 * qc;
        if (col0 < 40) {
            ls[r0][col0] = acc[s].x; ls[r0][col0 + 1] = acc[s].y;
            ls[r1][col0] = acc[s].z; ls[r1][col0 + 1] = acc[s].w;
        }
    }
    __syncthreads();

    // Warp-softmax: warp handles 8 rows
#pragma unroll
    for (int it = 0; it < 8; it++) {
        const int r = warp * 8 + it;
        const int node = nodeBase + r;
        if (node < N) {
            const float v0 = ls[r][lane];
            const float v1 = (lane < 8) ? ls[r][32 + lane] : 0.f;

            float m = (lane < 8) ? fmaxf(v0, v1) : v0;
#pragma unroll
            for (int off = 16; off; off >>= 1)
                m = fmaxf(m, __shfl_xor_sync(0xffffffffu, m, off));
            float s = expf(v0 - m) + ((lane < 8) ? expf(v1 - m) : 0.f);
#pragma unroll
            for (int off = 16; off; off >>= 1)
                s += __shfl_xor_sync(0xffffffffu, s, off);
            const float lse = m + logf(s);

            out[(size_t)node * 40 + lane] = v0 - lse;
            if (lane < 8)
                out[(size_t)node * 40 + 32 + lane] = v1 - lse;
        }
    }
}

// ---------------------------------------------------------------------------
// launch (single stream; block_scan at position 4 = env marker)
// ---------------------------------------------------------------------------
extern "C" void kernel_launch(void* const* d_in, const int* in_sizes, int n_in,
                              void* d_out, int out_size) {
    const float* x  = (const float*)d_in[0];
    const int*   er = (const int*)  d_in[1];
    const int*   ec = (const int*)  d_in[2];
    const float* ev = (const float*)d_in[3];
    const float* W1 = (const float*)d_in[4];
    const float* b1 = (const float*)d_in[5];
    const float* W2 = (const float*)d_in[6];
    const float* b2 = (const float*)d_in[7];
    const float* Wc = (const float*)d_in[8];
    const float* bc = (const float*)d_in[9];
    float* out = (float*)d_out;

    const int N = in_sizes[0] / IN_DIM;   // 100000
    const int E = in_sizes[1];            // 1600000

    void *pH_, *pH2_, *pB_, *pW1t_, *pW2t_, *pWct_, *pCnt_, *pPtr_, *pPar_, *pCsr_;
    cudaGetSymbolAddress(&pH_, g_h);
    cudaGetSymbolAddress(&pH2_, g_h2);
    cudaGetSymbolAddress(&pB_, g_B);
    cudaGetSymbolAddress(&pW1t_, g_w1t);
    cudaGetSymbolAddress(&pW2t_, g_w2t);
    cudaGetSymbolAddress(&pWct_, g_wct);
    cudaGetSymbolAddress(&pCnt_, g_cnt);
    cudaGetSymbolAddress(&pPtr_, g_ptr);
    cudaGetSymbolAddress(&pPar_, g_partials);
    cudaGetSymbolAddress(&pCsr_, g_csr);
    __half* Hh   = (__half*)pH_;
    __half* H2   = (__half*)pH2_;
    float*  B    = (float*)pB_;
    __half* W1t  = (__half*)pW1t_;
    __half* W2t  = (__half*)pW2t_;
    __half* Wct  = (__half*)pWct_;
    int*    cnt  = (int*)pCnt_;
    int*    ptr  = (int*)pPtr_;
    int*    par  = (int*)pPar_;
    int2*   csr  = (int2*)pCsr_;

    const int gemmBlocks = (N + 63) / 64;
    const int eBlocks    = (E + 255) / 256;
    const int spmmBlocks = (N + 31) / 32;     // 32 rows per 256-thread block

    // --- CSR build (block_scan = env marker at position 4) ---
    zero_int_kernel<<<(N + 255) / 256, 256>>>(cnt, N);
    hist_kernel<<<eBlocks, 256>>>(er, cnt, E);
    chunk_reduce_kernel<<<NCHUNK, CHUNK>>>(cnt, par, N);
    block_scan_kernel<<<NCHUNK, CHUNK>>>(cnt, par, ptr, cnt /*cursor*/, N, E);
    scatter_kernel<<<eBlocks, 256>>>(er, ec, ev, cnt, csr, E);

    // --- One-off weight transpose/convert ---
    convert_wt_kernel<<<((IN_DIM + HID + 48) * 64 + 255) / 256, 256>>>(
        W1, W2, Wc, W1t, W2t, Wct);

    // --- Layer 1: support1(fp16) = x@W1+b1 ; h1(fp32) = spmm ---
    gemm_f16mma_kernel<IN_DIM, false><<<gemmBlocks, 256>>>(x, W1t, b1, Hh, N);
    csr_spmm_h2f_kernel<<<spmmBlocks, 256>>>(ptr, csr, Hh, B, N);

    // --- Layer 2: support2(fp16) = relu(h1)@W2+b2 ; h2(fp16) = spmm ---
    gemm_f16mma_kernel<HID, true><<<gemmBlocks, 256>>>(B, W2t, b2, Hh, N);
    csr_spmm_h2h_kernel<<<spmmBlocks, 256>>>(ptr, csr, Hh, H2, N);

    // --- Classifier (fp16 MMA) + log-softmax ---
    classifier_mma_kernel<<<gemmBlocks, 256>>>(H2, Wct, bc, out, N);
}